// round 12
// baseline (speedup 1.0000x reference)
#include <cuda_runtime.h>
#include <math.h>
#include <stdint.h>

#define T   2048
#define H   16
#define DN  128
#define DR  64
#define DV  128
#define QL  1536
#define KVL 512
#define HID 5120
#define DQK 192            // DN + DR
#define DKV 256            // DN + DV
#define EPS 1e-6f
#define THETA 10000.0f

// ---------------- scratch (static __device__ — no runtime allocation) ----------------
__device__ float g_qa   [(size_t)T * QL];
__device__ float g_qan  [(size_t)T * QL];
__device__ float g_q    [(size_t)T * H * DQK];
__device__ float g_kv   [(size_t)T * (KVL + DR)];
__device__ float g_kvpart[(size_t)4 * T * (KVL + DR)];
__device__ float g_ckv  [(size_t)T * KVL];
__device__ float g_kvb  [(size_t)T * H * DKV];
__device__ float g_qcat [(size_t)H * T * DQK];
__device__ float g_kcat [(size_t)H * T * DQK];
__device__ float g_v    [(size_t)H * T * DV];
__device__ float g_scores[(size_t)H * T * T];     // 268 MB
__device__ float g_attnout[(size_t)T * H * DV];

// ---------------- helpers ----------------
__device__ __forceinline__ float to_tf32(float x) {
    float r;
    asm("cvt.rna.tf32.f32 %0, %1;" : "=f"(r) : "f"(x));
    return r;
}

__device__ __forceinline__ void mma_tf32(float* d, const float* a, const float* b) {
    asm volatile(
        "mma.sync.aligned.m16n8k8.row.col.f32.tf32.tf32.f32 "
        "{%0,%1,%2,%3},{%4,%5,%6,%7},{%8,%9},{%0,%1,%2,%3};"
        : "+f"(d[0]), "+f"(d[1]), "+f"(d[2]), "+f"(d[3])
        : "r"(__float_as_uint(a[0])), "r"(__float_as_uint(a[1])),
          "r"(__float_as_uint(a[2])), "r"(__float_as_uint(a[3])),
          "r"(__float_as_uint(b[0])), "r"(__float_as_uint(b[1])));
}

// ---------------- tf32 tensor-core GEMM: C = A*B (NN) or A*B^T (NT), batched over z --
// BM=128, BN=64, BK=16, 128 threads (4 warps, 2x2), warp tile 64x32.
// Double-buffered SMEM, register-staged prefetch, 1 syncthreads per tile.
// __launch_bounds__(128,4): 16 warps/SM for latency hiding.
// CAUSAL: skip output blocks strictly above the diagonal (64-col blocks vs 128-row).
// KLIM:   truncate K at (blockIdx.y+1)*128.
#define AS_STR 20   // As[m][k] (16->20 pad): bank = (4m+k)%32 -> conflict-free
#define BS_STR 20   // Bs[n][k]: same

template<int TRANSB, int CAUSAL, int KLIM>
__global__ __launch_bounds__(128, 4)
void mma_gemm(int M, int N, int K,
              const float* __restrict__ A, int lda, size_t strideA,
              const float* __restrict__ B, int ldb, size_t strideB,
              float* __restrict__ C, int ldc, size_t strideC)
{
    if (CAUSAL) {
        if ((int)blockIdx.x * 64 > (int)blockIdx.y * 128 + 127) return;
    }
    int Keff = K;
    if (KLIM) {
        int lim = ((int)blockIdx.y + 1) * 128;
        if (lim < Keff) Keff = lim;
    }

    A += (size_t)blockIdx.z * strideA;
    B += (size_t)blockIdx.z * strideB;
    C += (size_t)blockIdx.z * strideC;

    __shared__ float As[2][128 * AS_STR];
    __shared__ float Bs[2][64 * BS_STR];

    const int tid  = threadIdx.x;
    const int lane = tid & 31;
    const int warp = tid >> 5;
    const int wm   = warp >> 1;         // 0..1
    const int wn   = warp & 1;          // 0..1
    const int row0 = blockIdx.y * 128;
    const int col0 = blockIdx.x * 64;

    float acc[4][4][4];
    #pragma unroll
    for (int mi = 0; mi < 4; mi++)
        #pragma unroll
        for (int ni = 0; ni < 4; ni++)
            #pragma unroll
            for (int f = 0; f < 4; f++) acc[mi][ni][f] = 0.f;

    float4 stA[4], stB[2];

    // ---- global loads into staging regs (tile k0) ----
    auto ldgA = [&](int k0) {
        #pragma unroll
        for (int i = 0; i < 4; i++) {
            int idx = tid + 128 * i, m = idx >> 2, j = idx & 3;
            stA[i] = *reinterpret_cast<const float4*>(
                &A[(size_t)(row0 + m) * lda + k0 + 4 * j]);
        }
    };
    auto ldgB = [&](int k0) {
        if (TRANSB) {   // B is [N,K] row-major
            #pragma unroll
            for (int i = 0; i < 2; i++) {
                int idx = tid + 128 * i, n = idx >> 2, j = idx & 3;
                stB[i] = *reinterpret_cast<const float4*>(
                    &B[(size_t)(col0 + n) * ldb + k0 + 4 * j]);
            }
        } else {        // B is [K,N] row-major: gather transposed strips
            #pragma unroll
            for (int i = 0; i < 2; i++) {
                int idx = tid + 128 * i, n = idx & 63, kq = (idx >> 6) * 4;
                const float* bp = &B[(size_t)(k0 + kq) * ldb + col0 + n];
                stB[i] = make_float4(bp[0], bp[ldb], bp[2 * (size_t)ldb],
                                     bp[3 * (size_t)ldb]);
            }
        }
    };

    // ---- staging regs -> SMEM buffer (with tf32 rounding) ----
    auto stsA = [&](int buf) {
        #pragma unroll
        for (int i = 0; i < 4; i++) {
            int idx = tid + 128 * i, m = idx >> 2, j = idx & 3;
            *reinterpret_cast<float4*>(&As[buf][m * AS_STR + 4 * j]) =
                make_float4(to_tf32(stA[i].x), to_tf32(stA[i].y),
                            to_tf32(stA[i].z), to_tf32(stA[i].w));
        }
    };
    auto stsB = [&](int buf) {
        if (TRANSB) {
            #pragma unroll
            for (int i = 0; i < 2; i++) {
                int idx = tid + 128 * i, n = idx >> 2, j = idx & 3;
                *reinterpret_cast<float4*>(&Bs[buf][n * BS_STR + 4 * j]) =
                    make_float4(to_tf32(stB[i].x), to_tf32(stB[i].y),
                                to_tf32(stB[i].z), to_tf32(stB[i].w));
            }
        } else {
            #pragma unroll
            for (int i = 0; i < 2; i++) {
                int idx = tid + 128 * i, n = idx & 63, kq = (idx >> 6) * 4;
                *reinterpret_cast<float4*>(&Bs[buf][n * BS_STR + kq]) =
                    make_float4(to_tf32(stB[i].x), to_tf32(stB[i].y),
                                to_tf32(stB[i].z), to_tf32(stB[i].w));
            }
        }
    };

    auto compute = [&](int buf) {
        #pragma unroll
        for (int ks = 0; ks < 2; ks++) {
            const int kq = ks * 8 + (lane & 3);
            float a[4][4], b[4][2];
            #pragma unroll
            for (int mi = 0; mi < 4; mi++) {
                int r = wm * 64 + mi * 16 + (lane >> 2);
                a[mi][0] = As[buf][r * AS_STR + kq];
                a[mi][1] = As[buf][(r + 8) * AS_STR + kq];
                a[mi][2] = As[buf][r * AS_STR + kq + 4];
                a[mi][3] = As[buf][(r + 8) * AS_STR + kq + 4];
            }
            #pragma unroll
            for (int ni = 0; ni < 4; ni++) {
                int n = wn * 32 + ni * 8 + (lane >> 2);
                b[ni][0] = Bs[buf][n * BS_STR + kq];
                b[ni][1] = Bs[buf][n * BS_STR + kq + 4];
            }
            #pragma unroll
            for (int mi = 0; mi < 4; mi++)
                #pragma unroll
                for (int ni = 0; ni < 4; ni++)
                    mma_tf32(acc[mi][ni], a[mi], b[ni]);
        }
    };

    // ---- main loop: 2-stage pipeline, 1 sync per tile ----
    const int nt = Keff / 16;
    ldgA(0); ldgB(0);
    stsA(0); stsB(0);
    __syncthreads();
    for (int t = 0; t < nt; t++) {
        const int buf = t & 1;
        if (t + 1 < nt) { ldgA((t + 1) * 16); ldgB((t + 1) * 16); }
        compute(buf);
        if (t + 1 < nt) {
            stsA(buf ^ 1); stsB(buf ^ 1);
            __syncthreads();
        }
    }

    // ---- epilogue ----
    #pragma unroll
    for (int mi = 0; mi < 4; mi++) {
        #pragma unroll
        for (int ni = 0; ni < 4; ni++) {
            int r  = row0 + wm * 64 + mi * 16 + (lane >> 2);
            int cc = col0 + wn * 32 + ni * 8 + 2 * (lane & 3);
            if (cc < N) {
                *reinterpret_cast<float2*>(&C[(size_t)r * ldc + cc]) =
                    make_float2(acc[mi][ni][0], acc[mi][ni][1]);
                *reinterpret_cast<float2*>(&C[(size_t)(r + 8) * ldc + cc]) =
                    make_float2(acc[mi][ni][2], acc[mi][ni][3]);
            }
        }
    }
}

// ---------------- split-K reduction: out[i] = sum_{s<4} part[s*n + i] ----------------
__global__ __launch_bounds__(256)
void reduce4_kernel(const float* __restrict__ p, float* __restrict__ out, int n4)
{
    int i = blockIdx.x * blockDim.x + threadIdx.x;
    if (i < n4) {
        const float4* p4 = reinterpret_cast<const float4*>(p);
        float4 a = p4[i], b = p4[i + n4], c = p4[i + 2 * n4], d = p4[i + 3 * n4];
        float4 r = make_float4(a.x + b.x + c.x + d.x, a.y + b.y + c.y + d.y,
                               a.z + b.z + c.z + d.z, a.w + b.w + c.w + d.w);
        reinterpret_cast<float4*>(out)[i] = r;
    }
}

// ---------------- RMSNorm: one block per row ----------------
__global__ __launch_bounds__(256)
void rmsnorm_kernel(const float* __restrict__ x, const float* __restrict__ w,
                    float* __restrict__ y, int n, int ld_in, int ld_out)
{
    const int row = blockIdx.x;
    const float* xr = x + (size_t)row * ld_in;
    float* yr = y + (size_t)row * ld_out;

    float s = 0.f;
    for (int i = threadIdx.x; i < n; i += blockDim.x) { float v = xr[i]; s += v * v; }

    __shared__ float red[32];
    #pragma unroll
    for (int o = 16; o; o >>= 1) s += __shfl_xor_sync(~0u, s, o);
    if ((threadIdx.x & 31) == 0) red[threadIdx.x >> 5] = s;
    __syncthreads();
    if (threadIdx.x < 32) {
        s = (threadIdx.x < (blockDim.x >> 5)) ? red[threadIdx.x] : 0.f;
        #pragma unroll
        for (int o = 16; o; o >>= 1) s += __shfl_xor_sync(~0u, s, o);
        if (threadIdx.x == 0) red[0] = s;
    }
    __syncthreads();
    const float r = rsqrtf(red[0] / (float)n + EPS);
    for (int i = threadIdx.x; i < n; i += blockDim.x) yr[i] = xr[i] * r * w[i];
}

// ---------------- pack: build qcat (roped+scaled), kcat (roped), v; head-major ----------------
__global__ __launch_bounds__(256)
void pack_kernel()
{
    const int t = blockIdx.x;
    const float pos = (float)t;     // positions == arange(T) by construction

    __shared__ float cs[DR / 2], sn[DR / 2];
    if (threadIdx.x < DR / 2) {
        const float inv = powf(THETA, -(float)(2 * threadIdx.x) / (float)DR);
        const float f = pos * inv;
        cs[threadIdx.x] = cosf(f);
        sn[threadIdx.x] = sinf(f);
    }
    __syncthreads();

    const float scale = rsqrtf((float)DQK);

    for (int idx = threadIdx.x; idx < H * DQK; idx += blockDim.x) {
        const int h = idx / DQK, d = idx % DQK;
        float qv;
        const size_t qbase = (size_t)t * (H * DQK) + (size_t)h * DQK;
        if (d < DN) {
            qv = g_q[qbase + d];
        } else {
            const int j = d - DN, i = j >> 1;
            const float x1 = g_q[qbase + DN + 2 * i];
            const float x2 = g_q[qbase + DN + 2 * i + 1];
            qv = (j & 1) ? (x2 * cs[i] + x1 * sn[i]) : (x1 * cs[i] - x2 * sn[i]);
        }
        g_qcat[((size_t)h * T + t) * DQK + d] = qv * scale;

        float kvv;
        if (d < DN) {
            kvv = g_kvb[(size_t)t * (H * DKV) + (size_t)h * DKV + d];
        } else {
            const int j = d - DN, i = j >> 1;
            const float x1 = g_kv[(size_t)t * (KVL + DR) + KVL + 2 * i];
            const float x2 = g_kv[(size_t)t * (KVL + DR) + KVL + 2 * i + 1];
            kvv = (j & 1) ? (x2 * cs[i] + x1 * sn[i]) : (x1 * cs[i] - x2 * sn[i]);
        }
        g_kcat[((size_t)h * T + t) * DQK + d] = kvv;
    }
    for (int idx = threadIdx.x; idx < H * DV; idx += blockDim.x) {
        const int h = idx / DV, d = idx % DV;
        g_v[((size_t)h * T + t) * DV + d] =
            g_kvb[(size_t)t * (H * DKV) + (size_t)h * DKV + DN + d];
    }
}

// ------- causal softmax, SMEM row cache; zero-fill only to the 128 boundary -------
__global__ __launch_bounds__(256)
void softmax_kernel()
{
    const int t = blockIdx.x;
    const int h = blockIdx.y;
    float* row = g_scores + ((size_t)h * T + t) * T;
    const int n = t + 1;
    const int nup = (t & ~127) + 128;   // attn@V reads only cols < nup

    __shared__ float buf[T];
    __shared__ float red[32];

    float m = -INFINITY;
    for (int i = threadIdx.x; i < n; i += blockDim.x) {
        float v = row[i];
        buf[i] = v;
        m = fmaxf(m, v);
    }
    #pragma unroll
    for (int o = 16; o; o >>= 1) m = fmaxf(m, __shfl_xor_sync(~0u, m, o));
    if ((threadIdx.x & 31) == 0) red[threadIdx.x >> 5] = m;
    __syncthreads();
    if (threadIdx.x < 32) {
        m = (threadIdx.x < (blockDim.x >> 5)) ? red[threadIdx.x] : -INFINITY;
        #pragma unroll
        for (int o = 16; o; o >>= 1) m = fmaxf(m, __shfl_xor_sync(~0u, m, o));
        if (threadIdx.x == 0) red[0] = m;
    }
    __syncthreads();
    m = red[0];
    __syncthreads();

    float s = 0.f;
    for (int i = threadIdx.x; i < n; i += blockDim.x) {
        const float e = expf(buf[i] - m);
        buf[i] = e;
        s += e;
    }
    #pragma unroll
    for (int o = 16; o; o >>= 1) s += __shfl_xor_sync(~0u, s, o);
    if ((threadIdx.x & 31) == 0) red[threadIdx.x >> 5] = s;
    __syncthreads();
    if (threadIdx.x < 32) {
        s = (threadIdx.x < (blockDim.x >> 5)) ? red[threadIdx.x] : 0.f;
        #pragma unroll
        for (int o = 16; o; o >>= 1) s += __shfl_xor_sync(~0u, s, o);
        if (threadIdx.x == 0) red[0] = s;
    }
    __syncthreads();
    const float inv = 1.f / red[0];

    for (int i = threadIdx.x; i < n; i += blockDim.x) row[i] = buf[i] * inv;
    for (int i = n + threadIdx.x; i < nup; i += blockDim.x) row[i] = 0.f;
}

// ---------------- launch ----------------
static inline dim3 gemm_grid(int M, int N, int Z) {
    return dim3((N + 63) / 64, (M + 127) / 128, Z);
}

extern "C" void kernel_launch(void* const* d_in, const int* in_sizes, int n_in,
                              void* d_out, int out_size)
{
    (void)in_sizes; (void)n_in; (void)out_size;
    const float* hidden  = (const float*)d_in[1];
    const float* wq_a    = (const float*)d_in[2];
    const float* q_a_ln  = (const float*)d_in[3];
    const float* wq_b    = (const float*)d_in[4];
    const float* wkv_a   = (const float*)d_in[5];
    const float* kv_a_ln = (const float*)d_in[6];
    const float* wkv_b   = (const float*)d_in[7];
    const float* wo      = (const float*)d_in[8];
    float* out = (float*)d_out;

    float *qa, *qan, *q, *kv, *kvpart, *ckv, *kvb, *qcat, *kcat, *v, *scores, *attnout;
    cudaGetSymbolAddress((void**)&qa, g_qa);
    cudaGetSymbolAddress((void**)&qan, g_qan);
    cudaGetSymbolAddress((void**)&q, g_q);
    cudaGetSymbolAddress((void**)&kv, g_kv);
    cudaGetSymbolAddress((void**)&kvpart, g_kvpart);
    cudaGetSymbolAddress((void**)&ckv, g_ckv);
    cudaGetSymbolAddress((void**)&kvb, g_kvb);
    cudaGetSymbolAddress((void**)&qcat, g_qcat);
    cudaGetSymbolAddress((void**)&kcat, g_kcat);
    cudaGetSymbolAddress((void**)&v, g_v);
    cudaGetSymbolAddress((void**)&scores, g_scores);
    cudaGetSymbolAddress((void**)&attnout, g_attnout);

    // 1) q_a = hidden @ wq_a          [T,HID]x[HID,QL]
    mma_gemm<0,0,0><<<gemm_grid(T, QL, 1), 128>>>(T, QL, HID, hidden, HID, 0, wq_a, QL, 0, qa, QL, 0);
    // 2) rmsnorm(q_a)
    rmsnorm_kernel<<<T, 256>>>(qa, q_a_ln, qan, QL, QL, QL);
    // 3) q = qan @ wq_b               [T,QL]x[QL,H*DQK]
    mma_gemm<0,0,0><<<gemm_grid(T, H * DQK, 1), 128>>>(T, H * DQK, QL, qan, QL, 0, wq_b, H * DQK, 0, q, H * DQK, 0);
    // 4) kv = hidden @ wkv_a  — split-K x4 + deterministic reduce
    {
        const int KS = HID / 4;   // 1280
        mma_gemm<0,0,0><<<gemm_grid(T, KVL + DR, 4), 128>>>(T, KVL + DR, KS,
            hidden, HID, (size_t)KS,
            wkv_a, KVL + DR, (size_t)KS * (KVL + DR),
            kvpart, KVL + DR, (size_t)T * (KVL + DR));
        const int n4 = T * (KVL + DR) / 4;
        reduce4_kernel<<<(n4 + 255) / 256, 256>>>(kvpart, kv, n4);
    }
    // 5) c_kv = rmsnorm(kv[:, :KVL])
    rmsnorm_kernel<<<T, 256>>>(kv, kv_a_ln, ckv, KVL, KVL + DR, KVL);
    // 6) kvb = c_kv @ wkv_b           [T,KVL]x[KVL,H*DKV]
    mma_gemm<0,0,0><<<gemm_grid(T, H * DKV, 1), 128>>>(T, H * DKV, KVL, ckv, KVL, 0, wkv_b, H * DKV, 0, kvb, H * DKV, 0);
    // 7) pack qcat/kcat/v with fused RoPE + scale
    pack_kernel<<<T, 256>>>();
    // 8) scores[h] = qcat[h] @ kcat[h]^T   (batched NT, causal block skip)
    mma_gemm<1,1,0><<<gemm_grid(T, T, H), 128>>>(T, T, DQK,
        qcat, DQK, (size_t)T * DQK, kcat, DQK, (size_t)T * DQK, scores, T, (size_t)T * T);
    // 9) causal softmax (+ bounded zero tail)
    softmax_kernel<<<dim3(T, H), 256>>>();
    // 10) attnout[:, h*DV:(h+1)*DV] = attn[h] @ v[h]   (batched NN, K truncated)
    mma_gemm<0,0,1><<<gemm_grid(T, DV, H), 128>>>(T, DV, T,
        scores, T, (size_t)T * T, v, DV, (size_t)T * DV, attnout, H * DV, (size_t)DV);
    // 11) out = attnout @ wo          [T,H*DV]x[H*DV,HID]
    mma_gemm<0,0,0><<<gemm_grid(T, HID, 1), 128>>>(T, HID, H * DV, attnout, H * DV, 0, wo, HID, 0, out, HID, 0);
}

// round 17
// speedup vs baseline: 1.1039x; 1.1039x over previous
#include <cuda_runtime.h>
#include <math.h>
#include <stdint.h>

#define T   2048
#define H   16
#define DN  128
#define DR  64
#define DV  128
#define QL  1536
#define KVL 512
#define HID 5120
#define DQK 192            // DN + DR
#define DKV 256            // DN + DV
#define EPS 1e-6f
#define THETA 10000.0f

// ---------------- scratch (static __device__ — no runtime allocation) ----------------
__device__ float g_qa   [(size_t)T * QL];
__device__ float g_qan  [(size_t)T * QL];
__device__ float g_q    [(size_t)T * H * DQK];
__device__ float g_kv   [(size_t)T * (KVL + DR)];
__device__ float g_kvpart[(size_t)4 * T * (KVL + DR)];
__device__ float g_ckv  [(size_t)T * KVL];
__device__ float g_kvb  [(size_t)T * H * DKV];
__device__ float g_qcat [(size_t)H * T * DQK];
__device__ float g_kcat [(size_t)H * T * DQK];
__device__ float g_v    [(size_t)H * T * DV];
__device__ float g_scores[(size_t)H * T * T];     // 268 MB
__device__ float g_attnout[(size_t)T * H * DV];

// ---------------- helpers ----------------
__device__ __forceinline__ float to_tf32(float x) {
    float r;
    asm("cvt.rna.tf32.f32 %0, %1;" : "=f"(r) : "f"(x));
    return r;
}

__device__ __forceinline__ void mma_tf32(float* d, const float* a, const float* b) {
    asm volatile(
        "mma.sync.aligned.m16n8k8.row.col.f32.tf32.tf32.f32 "
        "{%0,%1,%2,%3},{%4,%5,%6,%7},{%8,%9},{%0,%1,%2,%3};"
        : "+f"(d[0]), "+f"(d[1]), "+f"(d[2]), "+f"(d[3])
        : "r"(__float_as_uint(a[0])), "r"(__float_as_uint(a[1])),
          "r"(__float_as_uint(a[2])), "r"(__float_as_uint(a[3])),
          "r"(__float_as_uint(b[0])), "r"(__float_as_uint(b[1])));
}

// ================= FAT GEMM (R4 config, measured best for large N) =================
// BM=BN=128, BK=16, 128 threads (4 warps, 2x2), warp tile 64x64.
// Double-buffered SMEM, register-staged prefetch, 1 sync per tile, occ 2.
#define AS_STR 20   // As[m][k] (16->20 pad): bank = (4m+k)%32 -> conflict-free
#define BS_STR 20   // Bs[n][k]: same

template<int TRANSB, int CAUSAL, int KLIM>
__global__ __launch_bounds__(128, 2)
void mma_gemm_f(int M, int N, int K,
                const float* __restrict__ A, int lda, size_t strideA,
                const float* __restrict__ B, int ldb, size_t strideB,
                float* __restrict__ C, int ldc, size_t strideC)
{
    if (CAUSAL) {
        if ((int)blockIdx.x * 128 > (int)blockIdx.y * 128 + 127) return;
    }
    int Keff = K;
    if (KLIM) {
        int lim = ((int)blockIdx.y + 1) * 128;
        if (lim < Keff) Keff = lim;
    }

    A += (size_t)blockIdx.z * strideA;
    B += (size_t)blockIdx.z * strideB;
    C += (size_t)blockIdx.z * strideC;

    __shared__ float As[2][128 * AS_STR];
    __shared__ float Bs[2][128 * BS_STR];

    const int tid  = threadIdx.x;
    const int lane = tid & 31;
    const int warp = tid >> 5;
    const int wm   = warp >> 1;         // 0..1
    const int wn   = warp & 1;          // 0..1
    const int row0 = blockIdx.y * 128;
    const int col0 = blockIdx.x * 128;

    float acc[4][8][4];
    #pragma unroll
    for (int mi = 0; mi < 4; mi++)
        #pragma unroll
        for (int ni = 0; ni < 8; ni++)
            #pragma unroll
            for (int f = 0; f < 4; f++) acc[mi][ni][f] = 0.f;

    float4 stA[4], stB[4];

    auto ldgA = [&](int k0) {
        #pragma unroll
        for (int i = 0; i < 4; i++) {
            int idx = tid + 128 * i, m = idx >> 2, j = idx & 3;
            stA[i] = *reinterpret_cast<const float4*>(
                &A[(size_t)(row0 + m) * lda + k0 + 4 * j]);
        }
    };
    auto ldgB = [&](int k0) {
        if (TRANSB) {   // B is [N,K] row-major
            #pragma unroll
            for (int i = 0; i < 4; i++) {
                int idx = tid + 128 * i, n = idx >> 2, j = idx & 3;
                stB[i] = *reinterpret_cast<const float4*>(
                    &B[(size_t)(col0 + n) * ldb + k0 + 4 * j]);
            }
        } else {        // B is [K,N] row-major: gather transposed strips
            #pragma unroll
            for (int i = 0; i < 4; i++) {
                int idx = tid + 128 * i, n = idx & 127, kq = (idx >> 7) * 4;
                const float* bp = &B[(size_t)(k0 + kq) * ldb + col0 + n];
                stB[i] = make_float4(bp[0], bp[ldb], bp[2 * (size_t)ldb],
                                     bp[3 * (size_t)ldb]);
            }
        }
    };

    auto stsA = [&](int buf) {
        #pragma unroll
        for (int i = 0; i < 4; i++) {
            int idx = tid + 128 * i, m = idx >> 2, j = idx & 3;
            *reinterpret_cast<float4*>(&As[buf][m * AS_STR + 4 * j]) =
                make_float4(to_tf32(stA[i].x), to_tf32(stA[i].y),
                            to_tf32(stA[i].z), to_tf32(stA[i].w));
        }
    };
    auto stsB = [&](int buf) {
        if (TRANSB) {
            #pragma unroll
            for (int i = 0; i < 4; i++) {
                int idx = tid + 128 * i, n = idx >> 2, j = idx & 3;
                *reinterpret_cast<float4*>(&Bs[buf][n * BS_STR + 4 * j]) =
                    make_float4(to_tf32(stB[i].x), to_tf32(stB[i].y),
                                to_tf32(stB[i].z), to_tf32(stB[i].w));
            }
        } else {
            #pragma unroll
            for (int i = 0; i < 4; i++) {
                int idx = tid + 128 * i, n = idx & 127, kq = (idx >> 7) * 4;
                *reinterpret_cast<float4*>(&Bs[buf][n * BS_STR + kq]) =
                    make_float4(to_tf32(stB[i].x), to_tf32(stB[i].y),
                                to_tf32(stB[i].z), to_tf32(stB[i].w));
            }
        }
    };

    auto compute = [&](int buf) {
        #pragma unroll
        for (int ks = 0; ks < 2; ks++) {
            const int kq = ks * 8 + (lane & 3);
            float a[4][4], b[8][2];
            #pragma unroll
            for (int mi = 0; mi < 4; mi++) {
                int r = wm * 64 + mi * 16 + (lane >> 2);
                a[mi][0] = As[buf][r * AS_STR + kq];
                a[mi][1] = As[buf][(r + 8) * AS_STR + kq];
                a[mi][2] = As[buf][r * AS_STR + kq + 4];
                a[mi][3] = As[buf][(r + 8) * AS_STR + kq + 4];
            }
            #pragma unroll
            for (int ni = 0; ni < 8; ni++) {
                int n = wn * 64 + ni * 8 + (lane >> 2);
                b[ni][0] = Bs[buf][n * BS_STR + kq];
                b[ni][1] = Bs[buf][n * BS_STR + kq + 4];
            }
            #pragma unroll
            for (int mi = 0; mi < 4; mi++)
                #pragma unroll
                for (int ni = 0; ni < 8; ni++)
                    mma_tf32(acc[mi][ni], a[mi], b[ni]);
        }
    };

    const int nt = Keff / 16;
    ldgA(0); ldgB(0);
    stsA(0); stsB(0);
    __syncthreads();
    for (int t = 0; t < nt; t++) {
        const int buf = t & 1;
        if (t + 1 < nt) { ldgA((t + 1) * 16); ldgB((t + 1) * 16); }
        compute(buf);
        if (t + 1 < nt) {
            stsA(buf ^ 1); stsB(buf ^ 1);
            __syncthreads();
        }
    }

    #pragma unroll
    for (int mi = 0; mi < 4; mi++) {
        #pragma unroll
        for (int ni = 0; ni < 8; ni++) {
            int r  = row0 + wm * 64 + mi * 16 + (lane >> 2);
            int cc = col0 + wn * 64 + ni * 8 + 2 * (lane & 3);
            if (cc < N) {
                *reinterpret_cast<float2*>(&C[(size_t)r * ldc + cc]) =
                    make_float2(acc[mi][ni][0], acc[mi][ni][1]);
                *reinterpret_cast<float2*>(&C[(size_t)(r + 8) * ldc + cc]) =
                    make_float2(acc[mi][ni][2], acc[mi][ni][3]);
            }
        }
    }
}

// ================= SKINNY GEMM (R6 config, measured best for kv_a) =================
// BM=128, BN=64, BK=16, 128 threads (4 warps, 2x2), warp tile 64x32, occ 4.
template<int TRANSB>
__global__ __launch_bounds__(128, 4)
void mma_gemm_s(int M, int N, int K,
                const float* __restrict__ A, int lda, size_t strideA,
                const float* __restrict__ B, int ldb, size_t strideB,
                float* __restrict__ C, int ldc, size_t strideC)
{
    A += (size_t)blockIdx.z * strideA;
    B += (size_t)blockIdx.z * strideB;
    C += (size_t)blockIdx.z * strideC;

    __shared__ float As[2][128 * AS_STR];
    __shared__ float Bs[2][64 * BS_STR];

    const int tid  = threadIdx.x;
    const int lane = tid & 31;
    const int warp = tid >> 5;
    const int wm   = warp >> 1;
    const int wn   = warp & 1;
    const int row0 = blockIdx.y * 128;
    const int col0 = blockIdx.x * 64;

    float acc[4][4][4];
    #pragma unroll
    for (int mi = 0; mi < 4; mi++)
        #pragma unroll
        for (int ni = 0; ni < 4; ni++)
            #pragma unroll
            for (int f = 0; f < 4; f++) acc[mi][ni][f] = 0.f;

    float4 stA[4], stB[2];

    auto ldgA = [&](int k0) {
        #pragma unroll
        for (int i = 0; i < 4; i++) {
            int idx = tid + 128 * i, m = idx >> 2, j = idx & 3;
            stA[i] = *reinterpret_cast<const float4*>(
                &A[(size_t)(row0 + m) * lda + k0 + 4 * j]);
        }
    };
    auto ldgB = [&](int k0) {
        if (TRANSB) {
            #pragma unroll
            for (int i = 0; i < 2; i++) {
                int idx = tid + 128 * i, n = idx >> 2, j = idx & 3;
                stB[i] = *reinterpret_cast<const float4*>(
                    &B[(size_t)(col0 + n) * ldb + k0 + 4 * j]);
            }
        } else {
            #pragma unroll
            for (int i = 0; i < 2; i++) {
                int idx = tid + 128 * i, n = idx & 63, kq = (idx >> 6) * 4;
                const float* bp = &B[(size_t)(k0 + kq) * ldb + col0 + n];
                stB[i] = make_float4(bp[0], bp[ldb], bp[2 * (size_t)ldb],
                                     bp[3 * (size_t)ldb]);
            }
        }
    };

    auto stsA = [&](int buf) {
        #pragma unroll
        for (int i = 0; i < 4; i++) {
            int idx = tid + 128 * i, m = idx >> 2, j = idx & 3;
            *reinterpret_cast<float4*>(&As[buf][m * AS_STR + 4 * j]) =
                make_float4(to_tf32(stA[i].x), to_tf32(stA[i].y),
                            to_tf32(stA[i].z), to_tf32(stA[i].w));
        }
    };
    auto stsB = [&](int buf) {
        if (TRANSB) {
            #pragma unroll
            for (int i = 0; i < 2; i++) {
                int idx = tid + 128 * i, n = idx >> 2, j = idx & 3;
                *reinterpret_cast<float4*>(&Bs[buf][n * BS_STR + 4 * j]) =
                    make_float4(to_tf32(stB[i].x), to_tf32(stB[i].y),
                                to_tf32(stB[i].z), to_tf32(stB[i].w));
            }
        } else {
            #pragma unroll
            for (int i = 0; i < 2; i++) {
                int idx = tid + 128 * i, n = idx & 63, kq = (idx >> 6) * 4;
                *reinterpret_cast<float4*>(&Bs[buf][n * BS_STR + kq]) =
                    make_float4(to_tf32(stB[i].x), to_tf32(stB[i].y),
                                to_tf32(stB[i].z), to_tf32(stB[i].w));
            }
        }
    };

    auto compute = [&](int buf) {
        #pragma unroll
        for (int ks = 0; ks < 2; ks++) {
            const int kq = ks * 8 + (lane & 3);
            float a[4][4], b[4][2];
            #pragma unroll
            for (int mi = 0; mi < 4; mi++) {
                int r = wm * 64 + mi * 16 + (lane >> 2);
                a[mi][0] = As[buf][r * AS_STR + kq];
                a[mi][1] = As[buf][(r + 8) * AS_STR + kq];
                a[mi][2] = As[buf][r * AS_STR + kq + 4];
                a[mi][3] = As[buf][(r + 8) * AS_STR + kq + 4];
            }
            #pragma unroll
            for (int ni = 0; ni < 4; ni++) {
                int n = wn * 32 + ni * 8 + (lane >> 2);
                b[ni][0] = Bs[buf][n * BS_STR + kq];
                b[ni][1] = Bs[buf][n * BS_STR + kq + 4];
            }
            #pragma unroll
            for (int mi = 0; mi < 4; mi++)
                #pragma unroll
                for (int ni = 0; ni < 4; ni++)
                    mma_tf32(acc[mi][ni], a[mi], b[ni]);
        }
    };

    const int nt = K / 16;
    ldgA(0); ldgB(0);
    stsA(0); stsB(0);
    __syncthreads();
    for (int t = 0; t < nt; t++) {
        const int buf = t & 1;
        if (t + 1 < nt) { ldgA((t + 1) * 16); ldgB((t + 1) * 16); }
        compute(buf);
        if (t + 1 < nt) {
            stsA(buf ^ 1); stsB(buf ^ 1);
            __syncthreads();
        }
    }

    #pragma unroll
    for (int mi = 0; mi < 4; mi++) {
        #pragma unroll
        for (int ni = 0; ni < 4; ni++) {
            int r  = row0 + wm * 64 + mi * 16 + (lane >> 2);
            int cc = col0 + wn * 32 + ni * 8 + 2 * (lane & 3);
            if (cc < N) {
                *reinterpret_cast<float2*>(&C[(size_t)r * ldc + cc]) =
                    make_float2(acc[mi][ni][0], acc[mi][ni][1]);
                *reinterpret_cast<float2*>(&C[(size_t)(r + 8) * ldc + cc]) =
                    make_float2(acc[mi][ni][2], acc[mi][ni][3]);
            }
        }
    }
}

// ---------------- split-K reduction: out[i] = sum_{s<4} part[s*n + i] ----------------
__global__ __launch_bounds__(256)
void reduce4_kernel(const float* __restrict__ p, float* __restrict__ out, int n4)
{
    int i = blockIdx.x * blockDim.x + threadIdx.x;
    if (i < n4) {
        const float4* p4 = reinterpret_cast<const float4*>(p);
        float4 a = p4[i], b = p4[i + n4], c = p4[i + 2 * n4], d = p4[i + 3 * n4];
        float4 r = make_float4(a.x + b.x + c.x + d.x, a.y + b.y + c.y + d.y,
                               a.z + b.z + c.z + d.z, a.w + b.w + c.w + d.w);
        reinterpret_cast<float4*>(out)[i] = r;
    }
}

// ---------------- RMSNorm: one block per row ----------------
__global__ __launch_bounds__(256)
void rmsnorm_kernel(const float* __restrict__ x, const float* __restrict__ w,
                    float* __restrict__ y, int n, int ld_in, int ld_out)
{
    const int row = blockIdx.x;
    const float* xr = x + (size_t)row * ld_in;
    float* yr = y + (size_t)row * ld_out;

    float s = 0.f;
    for (int i = threadIdx.x; i < n; i += blockDim.x) { float v = xr[i]; s += v * v; }

    __shared__ float red[32];
    #pragma unroll
    for (int o = 16; o; o >>= 1) s += __shfl_xor_sync(~0u, s, o);
    if ((threadIdx.x & 31) == 0) red[threadIdx.x >> 5] = s;
    __syncthreads();
    if (threadIdx.x < 32) {
        s = (threadIdx.x < (blockDim.x >> 5)) ? red[threadIdx.x] : 0.f;
        #pragma unroll
        for (int o = 16; o; o >>= 1) s += __shfl_xor_sync(~0u, s, o);
        if (threadIdx.x == 0) red[0] = s;
    }
    __syncthreads();
    const float r = rsqrtf(red[0] / (float)n + EPS);
    for (int i = threadIdx.x; i < n; i += blockDim.x) yr[i] = xr[i] * r * w[i];
}

// ---------------- pack: build qcat (roped+scaled), kcat (roped), v; head-major ----------------
__global__ __launch_bounds__(256)
void pack_kernel()
{
    const int t = blockIdx.x;
    const float pos = (float)t;     // positions == arange(T) by construction

    __shared__ float cs[DR / 2], sn[DR / 2];
    if (threadIdx.x < DR / 2) {
        const float inv = powf(THETA, -(float)(2 * threadIdx.x) / (float)DR);
        const float f = pos * inv;
        cs[threadIdx.x] = cosf(f);
        sn[threadIdx.x] = sinf(f);
    }
    __syncthreads();

    const float scale = rsqrtf((float)DQK);

    for (int idx = threadIdx.x; idx < H * DQK; idx += blockDim.x) {
        const int h = idx / DQK, d = idx % DQK;
        float qv;
        const size_t qbase = (size_t)t * (H * DQK) + (size_t)h * DQK;
        if (d < DN) {
            qv = g_q[qbase + d];
        } else {
            const int j = d - DN, i = j >> 1;
            const float x1 = g_q[qbase + DN + 2 * i];
            const float x2 = g_q[qbase + DN + 2 * i + 1];
            qv = (j & 1) ? (x2 * cs[i] + x1 * sn[i]) : (x1 * cs[i] - x2 * sn[i]);
        }
        g_qcat[((size_t)h * T + t) * DQK + d] = qv * scale;

        float kvv;
        if (d < DN) {
            kvv = g_kvb[(size_t)t * (H * DKV) + (size_t)h * DKV + d];
        } else {
            const int j = d - DN, i = j >> 1;
            const float x1 = g_kv[(size_t)t * (KVL + DR) + KVL + 2 * i];
            const float x2 = g_kv[(size_t)t * (KVL + DR) + KVL + 2 * i + 1];
            kvv = (j & 1) ? (x2 * cs[i] + x1 * sn[i]) : (x1 * cs[i] - x2 * sn[i]);
        }
        g_kcat[((size_t)h * T + t) * DQK + d] = kvv;
    }
    for (int idx = threadIdx.x; idx < H * DV; idx += blockDim.x) {
        const int h = idx / DV, d = idx % DV;
        g_v[((size_t)h * T + t) * DV + d] =
            g_kvb[(size_t)t * (H * DKV) + (size_t)h * DKV + DN + d];
    }
}

// ------- causal softmax, SMEM row cache; zero-fill only to the 128 boundary -------
__global__ __launch_bounds__(256)
void softmax_kernel()
{
    const int t = blockIdx.x;
    const int h = blockIdx.y;
    float* row = g_scores + ((size_t)h * T + t) * T;
    const int n = t + 1;
    const int nup = (t & ~127) + 128;   // attn@V reads only cols < nup

    __shared__ float buf[T];
    __shared__ float red[32];

    float m = -INFINITY;
    for (int i = threadIdx.x; i < n; i += blockDim.x) {
        float v = row[i];
        buf[i] = v;
        m = fmaxf(m, v);
    }
    #pragma unroll
    for (int o = 16; o; o >>= 1) m = fmaxf(m, __shfl_xor_sync(~0u, m, o));
    if ((threadIdx.x & 31) == 0) red[threadIdx.x >> 5] = m;
    __syncthreads();
    if (threadIdx.x < 32) {
        m = (threadIdx.x < (blockDim.x >> 5)) ? red[threadIdx.x] : -INFINITY;
        #pragma unroll
        for (int o = 16; o; o >>= 1) m = fmaxf(m, __shfl_xor_sync(~0u, m, o));
        if (threadIdx.x == 0) red[0] = m;
    }
    __syncthreads();
    m = red[0];
    __syncthreads();

    float s = 0.f;
    for (int i = threadIdx.x; i < n; i += blockDim.x) {
        const float e = expf(buf[i] - m);
        buf[i] = e;
        s += e;
    }
    #pragma unroll
    for (int o = 16; o; o >>= 1) s += __shfl_xor_sync(~0u, s, o);
    if ((threadIdx.x & 31) == 0) red[threadIdx.x >> 5] = s;
    __syncthreads();
    if (threadIdx.x < 32) {
        s = (threadIdx.x < (blockDim.x >> 5)) ? red[threadIdx.x] : 0.f;
        #pragma unroll
        for (int o = 16; o; o >>= 1) s += __shfl_xor_sync(~0u, s, o);
        if (threadIdx.x == 0) red[0] = s;
    }
    __syncthreads();
    const float inv = 1.f / red[0];

    for (int i = threadIdx.x; i < n; i += blockDim.x) row[i] = buf[i] * inv;
    for (int i = n + threadIdx.x; i < nup; i += blockDim.x) row[i] = 0.f;
}

// ---------------- launch ----------------
static inline dim3 grid_f(int M, int N, int Z) {
    return dim3((N + 127) / 128, (M + 127) / 128, Z);
}
static inline dim3 grid_s(int M, int N, int Z) {
    return dim3((N + 63) / 64, (M + 127) / 128, Z);
}

extern "C" void kernel_launch(void* const* d_in, const int* in_sizes, int n_in,
                              void* d_out, int out_size)
{
    (void)in_sizes; (void)n_in; (void)out_size;
    const float* hidden  = (const float*)d_in[1];
    const float* wq_a    = (const float*)d_in[2];
    const float* q_a_ln  = (const float*)d_in[3];
    const float* wq_b    = (const float*)d_in[4];
    const float* wkv_a   = (const float*)d_in[5];
    const float* kv_a_ln = (const float*)d_in[6];
    const float* wkv_b   = (const float*)d_in[7];
    const float* wo      = (const float*)d_in[8];
    float* out = (float*)d_out;

    float *qa, *qan, *q, *kv, *kvpart, *ckv, *kvb, *qcat, *kcat, *v, *scores, *attnout;
    cudaGetSymbolAddress((void**)&qa, g_qa);
    cudaGetSymbolAddress((void**)&qan, g_qan);
    cudaGetSymbolAddress((void**)&q, g_q);
    cudaGetSymbolAddress((void**)&kv, g_kv);
    cudaGetSymbolAddress((void**)&kvpart, g_kvpart);
    cudaGetSymbolAddress((void**)&ckv, g_ckv);
    cudaGetSymbolAddress((void**)&kvb, g_kvb);
    cudaGetSymbolAddress((void**)&qcat, g_qcat);
    cudaGetSymbolAddress((void**)&kcat, g_kcat);
    cudaGetSymbolAddress((void**)&v, g_v);
    cudaGetSymbolAddress((void**)&scores, g_scores);
    cudaGetSymbolAddress((void**)&attnout, g_attnout);

    // 1) q_a = hidden @ wq_a          [T,HID]x[HID,QL]    (fat)
    mma_gemm_f<0,0,0><<<grid_f(T, QL, 1), 128>>>(T, QL, HID, hidden, HID, 0, wq_a, QL, 0, qa, QL, 0);
    // 2) rmsnorm(q_a)
    rmsnorm_kernel<<<T, 256>>>(qa, q_a_ln, qan, QL, QL, QL);
    // 3) q = qan @ wq_b               [T,QL]x[QL,H*DQK]   (fat)
    mma_gemm_f<0,0,0><<<grid_f(T, H * DQK, 1), 128>>>(T, H * DQK, QL, qan, QL, 0, wq_b, H * DQK, 0, q, H * DQK, 0);
    // 4) kv = hidden @ wkv_a  — skinny config + split-K x4 + deterministic reduce
    {
        const int KS = HID / 4;   // 1280
        mma_gemm_s<0><<<grid_s(T, KVL + DR, 4), 128>>>(T, KVL + DR, KS,
            hidden, HID, (size_t)KS,
            wkv_a, KVL + DR, (size_t)KS * (KVL + DR),
            kvpart, KVL + DR, (size_t)T * (KVL + DR));
        const int n4 = T * (KVL + DR) / 4;
        reduce4_kernel<<<(n4 + 255) / 256, 256>>>(kvpart, kv, n4);
    }
    // 5) c_kv = rmsnorm(kv[:, :KVL])
    rmsnorm_kernel<<<T, 256>>>(kv, kv_a_ln, ckv, KVL, KVL + DR, KVL);
    // 6) kvb = c_kv @ wkv_b           [T,KVL]x[KVL,H*DKV] (fat)
    mma_gemm_f<0,0,0><<<grid_f(T, H * DKV, 1), 128>>>(T, H * DKV, KVL, ckv, KVL, 0, wkv_b, H * DKV, 0, kvb, H * DKV, 0);
    // 7) pack qcat/kcat/v with fused RoPE + scale
    pack_kernel<<<T, 256>>>();
    // 8) scores[h] = qcat[h] @ kcat[h]^T   (fat NT, causal block skip)
    mma_gemm_f<1,1,0><<<grid_f(T, T, H), 128>>>(T, T, DQK,
        qcat, DQK, (size_t)T * DQK, kcat, DQK, (size_t)T * DQK, scores, T, (size_t)T * T);
    // 9) causal softmax (+ bounded zero tail)
    softmax_kernel<<<dim3(T, H), 256>>>();
    // 10) attnout[:, h*DV:(h+1)*DV] = attn[h] @ v[h]   (fat NN, K truncated)
    mma_gemm_f<0,0,1><<<grid_f(T, DV, H), 128>>>(T, DV, T,
        scores, T, (size_t)T * T, v, DV, (size_t)T * DV, attnout, H * DV, (size_t)DV);
    // 11) out = attnout @ wo          [T,H*DV]x[H*DV,HID] (fat)
    mma_gemm_f<0,0,0><<<grid_f(T, HID, 1), 128>>>(T, HID, H * DV, attnout, H * DV, 0, wo, HID, 0, out, HID, 0);
}